// round 5
// baseline (speedup 1.0000x reference)
#include <cuda_runtime.h>
#include <cstdint>
#include <cstddef>

#define TS   64
#define BS   16
#define NP   1024
#define DIN  32
#define DOUT 16
#define HID  64
#define WPB  8       // warps (= particle rows) per block
#define NTHR (WPB*32)
#define GRID (BS*NP/WPB)   // 2048 blocks

// ---- persistent scratch ---------------------------------------------------
static __device__ float    g_x[2][BS*NP*DIN];
static __device__ float    g_s[BS*NP];
static __device__ float    g_logw[BS*NP];
static __device__ uint32_t g_keys[TS-1][2];
static __device__ float    g_sv[DIN];
static __device__ float    g_vy[DOUT];
static __device__ float    g_Kd[DOUT];
static __device__ float    g_cg[DIN];
static __device__ float    g_tab[256];     // gumbel upper bound per top-8-bit bucket
static __device__ uint32_t g_rotm[16];     // opaque rotate multipliers + literal 1
static __device__ int      g_cnt;          // last-block counter (starts 0)

// ---- threefry2x32 (reference form, init only) ------------------------------
__device__ __forceinline__ uint32_t rotl32(uint32_t x, uint32_t d) {
    return (x << d) | (x >> (32u - d));
}

__device__ __forceinline__ void tf2x32(uint32_t k0, uint32_t k1,
                                       uint32_t x0, uint32_t x1,
                                       uint32_t& o0, uint32_t& o1)
{
    uint32_t k2 = k0 ^ k1 ^ 0x1BD11BDAu;
    x0 += k0; x1 += k1;
#define TFR0(r) { x0 += x1; x1 = rotl32(x1, r); x1 ^= x0; }
    TFR0(13) TFR0(15) TFR0(26) TFR0(6)
    x0 += k1; x1 += k2 + 1u;
    TFR0(17) TFR0(29) TFR0(16) TFR0(24)
    x0 += k2; x1 += k0 + 2u;
    TFR0(13) TFR0(15) TFR0(26) TFR0(6)
    x0 += k0; x1 += k1 + 3u;
    TFR0(17) TFR0(29) TFR0(16) TFR0(24)
    x0 += k1; x1 += k2 + 4u;
    TFR0(13) TFR0(15) TFR0(26) TFR0(6)
    x0 += k2; x1 += k0 + 5u;
#undef TFR0
    o0 = x0; o1 = x1;
}

// gumbel = -log(-log(uniform(tiny,1))) — exact JAX arithmetic
__device__ __forceinline__ float gumbel_from_bits(uint32_t w)
{
    float f = __uint_as_float(0x3f800000u | (w >> 9)) - 1.0f;
    float u = f + 1.17549435e-38f;
    return -logf(-logf(u));
}

// ---- fast cipher: pipe-balanced. WIDE-mul rotates (fma pipe) alternate with
// funnel-shift rotates (alu pipe); multipliers from memory defeat folding.
__device__ __forceinline__ uint32_t tf_fast(
    uint32_t x1, uint32_t k0,
    uint32_t m13, uint32_t m26, uint32_t m17, uint32_t m16, uint32_t one,
    uint32_t kA1, uint32_t kB1, uint32_t kA2, uint32_t kB2,
    uint32_t kA3, uint32_t kB3, uint32_t kA4, uint32_t kB4,
    uint32_t kA5, uint32_t kB5)
{
    uint32_t x0 = k0;
#define RWID(m) { x0 = x1*one + x0; uint64_t p = (uint64_t)x1*(uint64_t)(m); \
                  x1 = (((uint32_t)p) | ((uint32_t)(p>>32))) ^ x0; }
#define RSHF(r) { x0 = x0 + x1; x1 = __funnelshift_l(x1, x1, (r)) ^ x0; }
    RWID(m13) RSHF(15) RWID(m26) RSHF(6)
    x0 += kA1; x1 += kB1;
    RWID(m17) RSHF(29) RWID(m16) RSHF(24)
    x0 += kA2; x1 += kB2;
    RWID(m13) RSHF(15) RWID(m26) RSHF(6)
    x0 += kA3; x1 += kB3;
    RWID(m17) RSHF(29) RWID(m16) RSHF(24)
    x0 += kA4; x1 += kB4;
    RWID(m13) RSHF(15) RWID(m26) RSHF(6)
    x0 += kA5; x1 += kB5;
#undef RWID
#undef RSHF
    return x0 ^ x1;
}

// ---- init -----------------------------------------------------------------
__global__ void init_kernel(const float* __restrict__ lvx,
                            const float* __restrict__ lvy,
                            const float* __restrict__ gb1,
                            const float* __restrict__ gW2,
                            const float* __restrict__ gb2)
{
    int t = threadIdx.x;
    if (t < DIN)  g_sv[t] = sqrtf(expf(lvx[t]));
    if (t < DOUT) {
        float v = expf(lvy[t]);
        g_vy[t] = v;
        g_Kd[t] = logf(__fmul_rn(6.283185307179586f, v));
    }
    if (t < DIN) {
        float a = 0.f;
        for (int h = 0; h < HID; h++) {
            float hv = fmaxf(gb1[h], 0.f);
            a = fmaf(hv, gW2[h*DIN + t], a);
        }
        g_cg[t] = __fadd_rn(a, gb2[t]);
    }
    if (t < TS-1) {
        uint32_t o0, o1;
        tf2x32(0u, 1u, 0u, (uint32_t)t, o0, o1);
        g_keys[t][0] = o0; g_keys[t][1] = o1;
    }
    if (t == 0) {
        g_rotm[0] = 1u << 13; g_rotm[1] = 1u << 26;
        g_rotm[2] = 1u << 17; g_rotm[3] = 1u << 16;
        g_rotm[8] = 1u;
        g_cnt = 0;
    }
    for (int i = t; i < 256; i += 64)
        g_tab[i] = gumbel_from_bits(((uint32_t)i << 24) | 0x00FFFFFFu) + 1e-3f;
}

// ---- fused per-step kernel ------------------------------------------------
__global__ void __launch_bounds__(NTHR, 6) fstep_kernel(
    int t,
    const float* __restrict__ eps_std,
    const float* __restrict__ y,
    const float* __restrict__ gW1, const float* __restrict__ gb1,
    const float* __restrict__ gW2, const float* __restrict__ gb2,
    const float* __restrict__ fW1, const float* __restrict__ fb1,
    const float* __restrict__ fW2, const float* __restrict__ fb2,
    float* __restrict__ out)
{
    __shared__ __align__(16) float s_lw[NP];
    __shared__ float s_tab[256];
    __shared__ float s_y[DOUT], s_vy[DOUT], s_Kd[DOUT];
    __shared__ float s_x[WPB][DIN], s_h[WPB][HID], s_yh[WPB][DOUT];
    __shared__ int s_last;

    const int tid  = threadIdx.x;
    const int w    = tid >> 5, lane = tid & 31;
    const int row  = blockIdx.x * WPB + w;       // = b*NP + n
    const int b    = row >> 10;
    const int n    = row & (NP-1);

    s_tab[tid] = g_tab[tid];
    if (tid < DOUT) {
        s_y[tid]  = y[((size_t)t*BS + b)*DOUT + tid];
        s_vy[tid] = g_vy[tid];
        s_Kd[tid] = g_Kd[tid];
    }
    if (t > 0) {
        float4* d = (float4*)s_lw;
        const float4* s = (const float4*)&g_logw[b*NP];
        for (int i = tid; i < NP/4; i += NTHR) d[i] = s[i];
    }
    __syncthreads();

    const int cur = t & 1, prv = cur ^ 1;
    const float* eps = &eps_std[(((size_t)t*BS + b)*NP + n)*DIN];
    const float NEG_INF = __int_as_float(0xff800000);

    float xr;   // this lane's dimension (d = lane) of the particle state

    if (t == 0) {
        xr = __fadd_rn(g_cg[lane], __fmul_rn(__ldg(eps + lane), g_sv[lane]));
    } else {
        // ---- categorical: doubly-pruned gumbel-argmax over 1024, ILP=2 ----
        const uint32_t k0 = g_keys[t-1][0], k1 = g_keys[t-1][1];
        const uint32_t k2 = k0 ^ k1 ^ 0x1BD11BDAu;
        const uint32_t m13 = g_rotm[0], m26 = g_rotm[1];
        const uint32_t m17 = g_rotm[2], m16 = g_rotm[3];
        const uint32_t one = g_rotm[8];
        const uint32_t kA1 = k1, kB1 = k2 + 1u;
        const uint32_t kA2 = k2, kB2 = k0 + 2u;
        const uint32_t kA3 = k0, kB3 = k1 + 3u;
        const uint32_t kA4 = k1, kB4 = k2 + 4u;
        const uint32_t kA5 = k1 ^ k0 ^ 0x1BD11BDAu, kB5 = k0 + 5u;  // = k2
        const float GMAX = s_tab[255];          // max possible gumbel (+slack)
        const float2* lwp = (const float2*)s_lw;

        float best = NEG_INF, bp = NEG_INF;
        float cut = NEG_INF;                    // = bp - GMAX (pre-cipher skip)
        int   bidx = NP;
        uint32_t bk = (((uint32_t)row) << 10) + k1 + (uint32_t)(2*lane);

        #pragma unroll 1
        for (int i = 0; i < NP/64; i++, bk += 64u) {
            const float2 lw = lwp[i*32 + lane];       // candidates c, c+1
            if (!__any_sync(0xffffffffu, fmaxf(lw.x, lw.y) > cut))
                continue;                              // whole warp-iter pruned
            const int c = i*64 + 2*lane;
            uint32_t bits1 = tf_fast(bk,      k0, m13,m26,m17,m16,one,
                                     kA1,kB1,kA2,kB2,kA3,kB3,kA4,kB4,kA5,kB5);
            uint32_t bits2 = tf_fast(bk + 1u, k0, m13,m26,m17,m16,one,
                                     kA1,kB1,kA2,kB2,kA3,kB3,kA4,kB4,kA5,kB5);
            const float ub1 = s_tab[bits1 >> 24] + lw.x;
            const float ub2 = s_tab[bits2 >> 24] + lw.y;
            const bool n1 = ub1 > bp, n2 = ub2 > bp;
            if (__any_sync(0xffffffffu, n1 | n2)) {
                if (n1) {
                    float sc = gumbel_from_bits(bits1) + lw.x;
                    if (sc > best) { best = sc; bidx = c; }
                }
                if (n2) {
                    float sc = gumbel_from_bits(bits2) + lw.y;
                    if (sc > best) { best = sc; bidx = c + 1; }
                }
                if (__any_sync(0xffffffffu, best > bp)) {
                    float mm = best;
                    #pragma unroll
                    for (int off = 16; off; off >>= 1)
                        mm = fmaxf(mm, __shfl_xor_sync(0xffffffffu, mm, off));
                    bp = mm;
                    cut = bp - GMAX;
                }
            }
        }
        // exact final reduce, first-occurrence tie-break
        #pragma unroll
        for (int off = 16; off; off >>= 1) {
            float ob = __shfl_xor_sync(0xffffffffu, best, off);
            int   oi = __shfl_xor_sync(0xffffffffu, bidx, off);
            if (ob > best || (ob == best && oi < bidx)) { best = ob; bidx = oi; }
        }
        const int p = bidx;   // all lanes agree after xor butterfly

        // ---- gather parent + g-FFN (chains identical to R1-R4) ----
        float xv = g_x[prv][((size_t)(b*NP + p))*DIN + lane];
        s_x[w][lane] = xv;
        __syncwarp();
        float a0 = 0.f, a1 = 0.f;
        const float* w1 = gW1 + lane;
        #pragma unroll
        for (int k = 0; k < DIN; k++) {
            float xk = s_x[w][k];
            a0 = fmaf(xk, __ldg(w1 + k*HID),      a0);
            a1 = fmaf(xk, __ldg(w1 + k*HID + 32), a1);
        }
        s_h[w][lane]      = fmaxf(__fadd_rn(a0, __ldg(gb1 + lane)),      0.f);
        s_h[w][lane + 32] = fmaxf(__fadd_rn(a1, __ldg(gb1 + lane + 32)), 0.f);
        __syncwarp();
        float a = 0.f;
        const float* w2 = gW2 + lane;
        #pragma unroll
        for (int h = 0; h < HID; h++)
            a = fmaf(s_h[w][h], __ldg(w2 + h*DIN), a);
        float go = __fadd_rn(a, __ldg(gb2 + lane));
        xr = __fadd_rn(go, __fmul_rn(__ldg(eps + lane), g_sv[lane]));
        __syncwarp();
    }

    // write state for next step
    g_x[cur][((size_t)(b*NP + n))*DIN + lane] = xr;
    s_x[w][lane] = xr;
    __syncwarp();

    // ---- f-FFN ----
    {
        float a0 = 0.f, a1 = 0.f;
        const float* w1 = fW1 + lane;
        #pragma unroll
        for (int k = 0; k < DIN; k++) {
            float xk = s_x[w][k];
            a0 = fmaf(xk, __ldg(w1 + k*HID),      a0);
            a1 = fmaf(xk, __ldg(w1 + k*HID + 32), a1);
        }
        s_h[w][lane]      = fmaxf(__fadd_rn(a0, __ldg(fb1 + lane)),      0.f);
        s_h[w][lane + 32] = fmaxf(__fadd_rn(a1, __ldg(fb1 + lane + 32)), 0.f);
    }
    __syncwarp();
    if (lane < DOUT) {
        float a = 0.f;
        const float* w2 = fW2 + lane;
        #pragma unroll
        for (int h = 0; h < HID; h++)
            a = fmaf(s_h[w][h], __ldg(w2 + h*DOUT), a);
        float yh = __fadd_rn(a, __ldg(fb2 + lane));
        out[(((size_t)t*BS + b)*NP + n)*DOUT + lane] = yh;
        s_yh[w][lane] = yh;
    }
    __syncwarp();
    if (lane == 0) {
        float acc = 0.f;
        #pragma unroll
        for (int j = 0; j < DOUT; j++) {
            float yh = s_yh[w][j];
            float d2 = yh - s_y[j];
            float q  = __fdiv_rn(__fmul_rn(d2, d2), s_vy[j]);
            acc = __fadd_rn(acc, __fadd_rn(q, s_Kd[j]));
        }
        g_s[row] = __fmul_rn(-0.5f, acc);
    }

    // ---- last-block tail: log_softmax per batch row (exact R1 chains) -----
    __syncthreads();
    if (tid == 0) {
        __threadfence();
        int old = atomicAdd(&g_cnt, 1);
        s_last = (old == (int)gridDim.x - 1) ? 1 : 0;
    }
    __syncthreads();
    if (s_last) {
        __threadfence();
        for (int b2 = w; b2 < BS; b2 += WPB) {
            const float* s = &g_s[b2*NP];
            float m = NEG_INF;
            for (int c = lane; c < NP; c += 32) m = fmaxf(m, s[c]);
            #pragma unroll
            for (int off = 16; off; off >>= 1)
                m = fmaxf(m, __shfl_xor_sync(0xffffffffu, m, off));
            float p = 0.f;
            for (int c = lane; c < NP; c += 32) p = __fadd_rn(p, expf(s[c] - m));
            #pragma unroll
            for (int off = 16; off; off >>= 1)
                p = __fadd_rn(p, __shfl_down_sync(0xffffffffu, p, off));
            float L = logf(p);
            L = __shfl_sync(0xffffffffu, L, 0);
            for (int c = lane; c < NP; c += 32)
                g_logw[b2*NP + c] = (s[c] - m) - L;
        }
        __syncthreads();
        if (tid == 0) atomicExch(&g_cnt, 0);
    }
}

// ---- launch ---------------------------------------------------------------
extern "C" void kernel_launch(void* const* d_in, const int* in_sizes, int n_in,
                              void* d_out, int out_size)
{
    (void)in_sizes; (void)n_in; (void)out_size;
    const float* y    = (const float*)d_in[1];
    const float* eps  = (const float*)d_in[2];
    const float* lvx  = (const float*)d_in[3];
    const float* lvy  = (const float*)d_in[4];
    const float* gW1  = (const float*)d_in[5];
    const float* gb1  = (const float*)d_in[6];
    const float* gW2  = (const float*)d_in[7];
    const float* gb2  = (const float*)d_in[8];
    const float* fW1  = (const float*)d_in[9];
    const float* fb1  = (const float*)d_in[10];
    const float* fW2  = (const float*)d_in[11];
    const float* fb2  = (const float*)d_in[12];
    float* out = (float*)d_out;

    init_kernel<<<1, 64>>>(lvx, lvy, gb1, gW2, gb2);
    for (int t = 0; t < TS; t++) {
        fstep_kernel<<<GRID, NTHR>>>(t, eps, y, gW1, gb1, gW2, gb2,
                                     fW1, fb1, fW2, fb2, out);
    }
}

// round 8
// speedup vs baseline: 1.0305x; 1.0305x over previous
#include <cuda_runtime.h>
#include <cstdint>
#include <cstddef>

#define TS   64
#define BS   16
#define NP   1024
#define DIN  32
#define DOUT 16
#define HID  64
#define WPB  8       // warps (= particle rows) per block
#define NTHR (WPB*32)
#define GRID (BS*NP/WPB)   // 2048 blocks

// ---- persistent scratch ---------------------------------------------------
static __device__ float    g_x[2][BS*NP*DIN];
static __device__ float    g_s[BS*NP];
static __device__ float    g_logw[BS*NP];
static __device__ uint32_t g_keys[TS-1][2];
static __device__ float    g_sv[DIN];
static __device__ float    g_vy[DOUT];
static __device__ float    g_Kd[DOUT];
static __device__ float    g_cg[DIN];
static __device__ uint32_t g_rotm[16];     // opaque rotate multipliers + literal 1
static __device__ int      g_cnt;          // last-block counter (starts 0)

// ---- threefry2x32 (reference form, init only) ------------------------------
__device__ __forceinline__ uint32_t rotl32(uint32_t x, uint32_t d) {
    return (x << d) | (x >> (32u - d));
}

__device__ __forceinline__ void tf2x32(uint32_t k0, uint32_t k1,
                                       uint32_t x0, uint32_t x1,
                                       uint32_t& o0, uint32_t& o1)
{
    uint32_t k2 = k0 ^ k1 ^ 0x1BD11BDAu;
    x0 += k0; x1 += k1;
#define TFR0(r) { x0 += x1; x1 = rotl32(x1, r); x1 ^= x0; }
    TFR0(13) TFR0(15) TFR0(26) TFR0(6)
    x0 += k1; x1 += k2 + 1u;
    TFR0(17) TFR0(29) TFR0(16) TFR0(24)
    x0 += k2; x1 += k0 + 2u;
    TFR0(13) TFR0(15) TFR0(26) TFR0(6)
    x0 += k0; x1 += k1 + 3u;
    TFR0(17) TFR0(29) TFR0(16) TFR0(24)
    x0 += k1; x1 += k2 + 4u;
    TFR0(13) TFR0(15) TFR0(26) TFR0(6)
    x0 += k2; x1 += k0 + 5u;
#undef TFR0
    o0 = x0; o1 = x1;
}

// gumbel = -log(-log(uniform(tiny,1))) — exact JAX arithmetic
__device__ __forceinline__ float gumbel_from_bits(uint32_t w)
{
    float f = __uint_as_float(0x3f800000u | (w >> 9)) - 1.0f;
    float u = f + 1.17549435e-38f;
    return -logf(-logf(u));
}

// ---- fast cipher (R4 form: all rotates via IMAD.WIDE on fma pipe) ----------
__device__ __forceinline__ uint32_t tf_fast(
    uint32_t x1, uint32_t k0,
    uint32_t m13, uint32_t m15, uint32_t m26, uint32_t m6,
    uint32_t m17, uint32_t m29, uint32_t m16, uint32_t m24,
    uint32_t one,
    uint32_t kA1, uint32_t kB1, uint32_t kA2, uint32_t kB2,
    uint32_t kA3, uint32_t kB3, uint32_t kA4, uint32_t kB4,
    uint32_t kA5, uint32_t kB5)
{
    uint32_t x0 = k0;
#define RMAD(m) { x0 = x1*one + x0; uint64_t p = (uint64_t)x1*(uint64_t)(m); \
                  x1 = (((uint32_t)p) | ((uint32_t)(p>>32))) ^ x0; }
#define RADD(m) { x0 = x0 + x1;     uint64_t p = (uint64_t)x1*(uint64_t)(m); \
                  x1 = (((uint32_t)p) | ((uint32_t)(p>>32))) ^ x0; }
    RMAD(m13) RMAD(m15) RMAD(m26) RADD(m6)
    x0 += kA1; x1 += kB1;
    RMAD(m17) RMAD(m29) RMAD(m16) RADD(m24)
    x0 += kA2; x1 += kB2;
    RMAD(m13) RMAD(m15) RMAD(m26) RADD(m6)
    x0 += kA3; x1 += kB3;
    RMAD(m17) RMAD(m29) RMAD(m16) RADD(m24)
    x0 += kA4; x1 += kB4;
    RMAD(m13) RMAD(m15) RMAD(m26) RADD(m6)
    x0 += kA5; x1 += kB5;
#undef RMAD
#undef RADD
    return x0 ^ x1;
}

// ---- init -----------------------------------------------------------------
__global__ void init_kernel(const float* __restrict__ lvx,
                            const float* __restrict__ lvy,
                            const float* __restrict__ gb1,
                            const float* __restrict__ gW2,
                            const float* __restrict__ gb2)
{
    int t = threadIdx.x;
    if (t < DIN)  g_sv[t] = sqrtf(expf(lvx[t]));
    if (t < DOUT) {
        float v = expf(lvy[t]);
        g_vy[t] = v;
        g_Kd[t] = logf(__fmul_rn(6.283185307179586f, v));
    }
    if (t < DIN) {
        float a = 0.f;
        for (int h = 0; h < HID; h++) {
            float hv = fmaxf(gb1[h], 0.f);
            a = fmaf(hv, gW2[h*DIN + t], a);
        }
        g_cg[t] = __fadd_rn(a, gb2[t]);
    }
    if (t < TS-1) {
        uint32_t o0, o1;
        tf2x32(0u, 1u, 0u, (uint32_t)t, o0, o1);
        g_keys[t][0] = o0; g_keys[t][1] = o1;
    }
    if (t == 0) {
        const int rr[8] = {13, 15, 26, 6, 17, 29, 16, 24};
        for (int i = 0; i < 8; i++) g_rotm[i] = 1u << rr[i];
        g_rotm[8] = 1u;
        g_cnt = 0;
    }
}

// ---- fused per-step kernel ------------------------------------------------
__global__ void __launch_bounds__(NTHR, 6) fstep_kernel(
    int t,
    const float* __restrict__ eps_std,
    const float* __restrict__ y,
    const float* __restrict__ gW1, const float* __restrict__ gb1,
    const float* __restrict__ gW2, const float* __restrict__ gb2,
    const float* __restrict__ fW1, const float* __restrict__ fb1,
    const float* __restrict__ fW2, const float* __restrict__ fb2,
    float* __restrict__ out)
{
    __shared__ __align__(16) float s_lw[NP];
    __shared__ float s_y[DOUT], s_vy[DOUT], s_Kd[DOUT];
    __shared__ float s_x[WPB][DIN], s_h[WPB][HID], s_yh[WPB][DOUT];
    __shared__ int s_last;

    const int tid  = threadIdx.x;
    const int w    = tid >> 5, lane = tid & 31;
    const int row  = blockIdx.x * WPB + w;       // = b*NP + n
    const int b    = row >> 10;
    const int n    = row & (NP-1);

    if (tid < DOUT) {
        s_y[tid]  = y[((size_t)t*BS + b)*DOUT + tid];
        s_vy[tid] = g_vy[tid];
        s_Kd[tid] = g_Kd[tid];
    }
    if (t > 0) {
        float4* d = (float4*)s_lw;
        const float4* s = (const float4*)&g_logw[b*NP];
        for (int i = tid; i < NP/4; i += NTHR) d[i] = s[i];
    }
    __syncthreads();

    const int cur = t & 1, prv = cur ^ 1;
    const float* eps = &eps_std[(((size_t)t*BS + b)*NP + n)*DIN];
    const float NEG_INF = __int_as_float(0xff800000);

    float xr;   // this lane's dimension (d = lane) of the particle state

    if (t == 0) {
        xr = __fadd_rn(g_cg[lane], __fmul_rn(__ldg(eps + lane), g_sv[lane]));
    } else {
        // ---- categorical: FLO-pruned gumbel-argmax over 1024, ILP=2 -------
        const uint32_t k0 = g_keys[t-1][0], k1 = g_keys[t-1][1];
        const uint32_t k2 = k0 ^ k1 ^ 0x1BD11BDAu;
        const uint32_t m13 = g_rotm[0], m15 = g_rotm[1], m26 = g_rotm[2], m6  = g_rotm[3];
        const uint32_t m17 = g_rotm[4], m29 = g_rotm[5], m16 = g_rotm[6], m24 = g_rotm[7];
        const uint32_t one = g_rotm[8];
        const uint32_t kA1 = k1, kB1 = k2 + 1u;
        const uint32_t kA2 = k2, kB2 = k0 + 2u;
        const uint32_t kA3 = k0, kB3 = k1 + 3u;
        const uint32_t kA4 = k1, kB4 = k2 + 4u;
        const uint32_t kA5 = k1 ^ k0 ^ 0x1BD11BDAu, kB5 = k0 + 5u;  // = k2
        const float LN2U = 0.6931473f;          // >= ln2 (rounded up)
        const float2* lwp = (const float2*)s_lw;

        float best = NEG_INF;
        float bps  = NEG_INF;                   // = warp-best − slack (prune ref)
        int   bidx = NP;
        uint32_t bk = (((uint32_t)row) << 10) + k1 + (uint32_t)(2*lane);

        #pragma unroll 1
        for (int i = 0; i < NP/64; i++, bk += 64u) {
            const int c = i*64 + 2*lane;
            uint32_t bits1 = tf_fast(bk,      k0, m13,m15,m26,m6,m17,m29,m16,m24,one,
                                     kA1,kB1,kA2,kB2,kA3,kB3,kA4,kB4,kA5,kB5);
            uint32_t bits2 = tf_fast(bk + 1u, k0, m13,m15,m26,m6,m17,m29,m16,m24,one,
                                     kA1,kB1,kA2,kB2,kA3,kB3,kA4,kB4,kA5,kB5);
            const float2 lw = lwp[i*32 + lane];       // candidates c, c+1
            // mantissa = top 23 bits of 'bits'; j = its leading-ones count
            // (clz of the whole word only over-counts when the top 23 are all
            //  ones, which only RAISES the bound -> conservative).
            //   f < 1 - 2^-(j+1)  =>  1-u > 2^-(j+1)
            //   gumbel = -log(-log u) <= -log(1-u) < (j+1)*ln2
            const int j1 = __clz(~bits1);
            const int j2 = __clz(~bits2);
            const float ub1 = fmaf((float)(j1 + 1), LN2U, lw.x);
            const float ub2 = fmaf((float)(j2 + 1), LN2U, lw.y);
            const bool n1 = ub1 > bps, n2 = ub2 > bps;
            if (__any_sync(0xffffffffu, n1 | n2)) {
                if (n1) {
                    float sc = gumbel_from_bits(bits1) + lw.x;
                    if (sc > best) { best = sc; bidx = c; }
                }
                if (n2) {
                    float sc = gumbel_from_bits(bits2) + lw.y;
                    if (sc > best) { best = sc; bidx = c + 1; }
                }
                float mm = best;
                #pragma unroll
                for (int off = 16; off; off >>= 1)
                    mm = fmaxf(mm, __shfl_xor_sync(0xffffffffu, mm, off));
                bps = mm - 0.011f;   // slack: float rounding + tie safety
            }
        }
        // exact final reduce, first-occurrence tie-break
        #pragma unroll
        for (int off = 16; off; off >>= 1) {
            float ob = __shfl_xor_sync(0xffffffffu, best, off);
            int   oi = __shfl_xor_sync(0xffffffffu, bidx, off);
            if (ob > best || (ob == best && oi < bidx)) { best = ob; bidx = oi; }
        }
        const int p = bidx;   // all lanes agree after xor butterfly

        // ---- gather parent + g-FFN (chains identical to R1-R5) ----
        float xv = g_x[prv][((size_t)(b*NP + p))*DIN + lane];
        s_x[w][lane] = xv;
        __syncwarp();
        float a0 = 0.f, a1 = 0.f;
        const float* w1 = gW1 + lane;
        #pragma unroll
        for (int k = 0; k < DIN; k++) {
            float xk = s_x[w][k];
            a0 = fmaf(xk, __ldg(w1 + k*HID),      a0);
            a1 = fmaf(xk, __ldg(w1 + k*HID + 32), a1);
        }
        s_h[w][lane]      = fmaxf(__fadd_rn(a0, __ldg(gb1 + lane)),      0.f);
        s_h[w][lane + 32] = fmaxf(__fadd_rn(a1, __ldg(gb1 + lane + 32)), 0.f);
        __syncwarp();
        float a = 0.f;
        const float* w2 = gW2 + lane;
        #pragma unroll
        for (int h = 0; h < HID; h++)
            a = fmaf(s_h[w][h], __ldg(w2 + h*DIN), a);
        float go = __fadd_rn(a, __ldg(gb2 + lane));
        xr = __fadd_rn(go, __fmul_rn(__ldg(eps + lane), g_sv[lane]));
        __syncwarp();
    }

    // write state for next step
    g_x[cur][((size_t)(b*NP + n))*DIN + lane] = xr;
    s_x[w][lane] = xr;
    __syncwarp();

    // ---- f-FFN ----
    {
        float a0 = 0.f, a1 = 0.f;
        const float* w1 = fW1 + lane;
        #pragma unroll
        for (int k = 0; k < DIN; k++) {
            float xk = s_x[w][k];
            a0 = fmaf(xk, __ldg(w1 + k*HID),      a0);
            a1 = fmaf(xk, __ldg(w1 + k*HID + 32), a1);
        }
        s_h[w][lane]      = fmaxf(__fadd_rn(a0, __ldg(fb1 + lane)),      0.f);
        s_h[w][lane + 32] = fmaxf(__fadd_rn(a1, __ldg(fb1 + lane + 32)), 0.f);
    }
    __syncwarp();
    if (lane < DOUT) {
        float a = 0.f;
        const float* w2 = fW2 + lane;
        #pragma unroll
        for (int h = 0; h < HID; h++)
            a = fmaf(s_h[w][h], __ldg(w2 + h*DOUT), a);
        float yh = __fadd_rn(a, __ldg(fb2 + lane));
        out[(((size_t)t*BS + b)*NP + n)*DOUT + lane] = yh;
        s_yh[w][lane] = yh;
    }
    __syncwarp();
    if (lane == 0) {
        float acc = 0.f;
        #pragma unroll
        for (int j = 0; j < DOUT; j++) {
            float yh = s_yh[w][j];
            float d2 = yh - s_y[j];
            float q  = __fdiv_rn(__fmul_rn(d2, d2), s_vy[j]);
            acc = __fadd_rn(acc, __fadd_rn(q, s_Kd[j]));
        }
        g_s[row] = __fmul_rn(-0.5f, acc);
    }

    // ---- last-block tail: log_softmax per batch row (exact R1 chains) -----
    __syncthreads();
    if (tid == 0) {
        __threadfence();
        int old = atomicAdd(&g_cnt, 1);
        s_last = (old == (int)gridDim.x - 1) ? 1 : 0;
    }
    __syncthreads();
    if (s_last) {
        __threadfence();
        for (int b2 = w; b2 < BS; b2 += WPB) {
            const float* s = &g_s[b2*NP];
            float m = NEG_INF;
            for (int c = lane; c < NP; c += 32) m = fmaxf(m, s[c]);
            #pragma unroll
            for (int off = 16; off; off >>= 1)
                m = fmaxf(m, __shfl_xor_sync(0xffffffffu, m, off));
            float p = 0.f;
            for (int c = lane; c < NP; c += 32) p = __fadd_rn(p, expf(s[c] - m));
            #pragma unroll
            for (int off = 16; off; off >>= 1)
                p = __fadd_rn(p, __shfl_down_sync(0xffffffffu, p, off));
            float L = logf(p);
            L = __shfl_sync(0xffffffffu, L, 0);
            for (int c = lane; c < NP; c += 32)
                g_logw[b2*NP + c] = (s[c] - m) - L;
        }
        __syncthreads();
        if (tid == 0) atomicExch(&g_cnt, 0);
    }
}

// ---- launch ---------------------------------------------------------------
extern "C" void kernel_launch(void* const* d_in, const int* in_sizes, int n_in,
                              void* d_out, int out_size)
{
    (void)in_sizes; (void)n_in; (void)out_size;
    const float* y    = (const float*)d_in[1];
    const float* eps  = (const float*)d_in[2];
    const float* lvx  = (const float*)d_in[3];
    const float* lvy  = (const float*)d_in[4];
    const float* gW1  = (const float*)d_in[5];
    const float* gb1  = (const float*)d_in[6];
    const float* gW2  = (const float*)d_in[7];
    const float* gb2  = (const float*)d_in[8];
    const float* fW1  = (const float*)d_in[9];
    const float* fb1  = (const float*)d_in[10];
    const float* fW2  = (const float*)d_in[11];
    const float* fb2  = (const float*)d_in[12];
    float* out = (float*)d_out;

    init_kernel<<<1, 64>>>(lvx, lvy, gb1, gW2, gb2);
    for (int t = 0; t < TS; t++) {
        fstep_kernel<<<GRID, NTHR>>>(t, eps, y, gW1, gb1, gW2, gb2,
                                     fW1, fb1, fW2, fb2, out);
    }
}